// round 17
// baseline (speedup 1.0000x reference)
#include <cuda_runtime.h>
#include <math.h>

#define BATCH 256
#define TLEN  50
#define NOBS  8192
#define NKC   50
#define REP   16      // state replication factor (bank-conflict mitigation)

// ---- device-global scratch (no allocations allowed) ----
__device__ unsigned char g_assign[NOBS];                 // assign[] as uint8
__device__ float         g_probs_scratch[BATCH * TLEN];  // fallback sink

__device__ __forceinline__ float sigm(float x) {
    return 1.0f / (1.0f + __expf(-x));
}

__device__ __forceinline__ void l2_prefetch(const void* p) {
    asm volatile("prefetch.global.L2 [%0];" :: "l"(p));
}

// ============================================================
// k1: recover assign[] from one-hot A (100 blocks x 256, single
// wave, MLP=4) AND prefetch k2's input arrays into L2 so k2's
// head loads are L2 hits instead of cold DRAM.
// ============================================================
__global__ __launch_bounds__(256)
void k1_prep(const float4* __restrict__ A4,
             const int*    __restrict__ prev_kc,
             const int*    __restrict__ curr_kc,
             const float*  __restrict__ prev_corr,
             const float*  __restrict__ kc_logits) {
    const int stride = 100 * 256;                 // 25600 threads
    int t = blockIdx.x * 256 + threadIdx.x;

    // ---- L2 prefetch of k2 inputs (no data dependency) ----
    // each array = 12800 x 4B = 3200 cache-line-spaced float4s
    if (t < 3200) {
        l2_prefetch((const char*)prev_kc   + t * 16);
        l2_prefetch((const char*)curr_kc   + t * 16);
        l2_prefetch((const char*)prev_corr + t * 16);
    }
    if (t < 63) l2_prefetch((const char*)kc_logits + t * 16);   // 250 floats

    // ---- assign recovery (4 independent float4 loads) ----
    #pragma unroll
    for (int j = 0; j < 4; j++) {
        int idx = t + stride * j;                 // < 102400
        float4 v = A4[idx];
        int base = idx * 4;
        if (v.x > 0.5f) { int i = base + 0; g_assign[i / NKC] = (unsigned char)(i % NKC); }
        if (v.y > 0.5f) { int i = base + 1; g_assign[i / NKC] = (unsigned char)(i % NKC); }
        if (v.z > 0.5f) { int i = base + 2; g_assign[i / NKC] = (unsigned char)(i % NKC); }
        if (v.w > 0.5f) { int i = base + 3; g_assign[i / NKC] = (unsigned char)(i % NKC); }
    }
}

// ============================================================
// k2: 128 blocks x 512 threads (single wave), 2 rows/block.
//  - head loads now L2-hot (k1 prefetched them)
//  - direct L2 gathers of assign[pk]/assign[ck]
//  - vector-apply Moebius composition (4 FMA + 2 SEL per step)
//  - expansion via x16-replicated state table (conflict <= 2)
// ============================================================
__global__ __launch_bounds__(512)
void k2_fused(const int*   __restrict__ prev_kc,
              const int*   __restrict__ curr_kc,
              const float* __restrict__ prev_corr,
              const float* __restrict__ kc_logits,
              float*       __restrict__ probs_out,
              float*       __restrict__ state_out,
              int do_state) {
    __shared__ unsigned char s_assign[NOBS];       // 8 KB (expansion only)
    __shared__ float4        s_pr[NKC];
    __shared__ float         s_p4[NKC];
    __shared__ float4        s_M[2][TLEN];
    __shared__ float2        s_ozw[2][TLEN];
    __shared__ float         s_rep[2][NKC * REP];  // replicated final state
    __shared__ unsigned char s_ap[2][TLEN];
    __shared__ unsigned char s_ack[2][TLEN];

    const int tid = threadIdx.x;
    const int r   = tid >> 8;          // row half
    const int rt  = tid & 255;
    const int b   = blockIdx.x * 2 + r;

    // ---- issue scalar row loads first (L2-hot after k1) ----
    int   pkv = 0, ckv = 0;
    float cr  = 0.0f;
    if (rt < TLEN) {
        pkv = prev_kc[b * TLEN + rt];
        ckv = curr_kc[b * TLEN + rt];
        cr  = prev_corr[b * TLEN + rt];
    }

    // ---- s_assign copy (one int4/thread = 8 KB; overlaps) ----
    {
        const int4* src = (const int4*)g_assign;
        ((int4*)s_assign)[tid] = src[tid];
    }

    // ---- sigmoids (once per block) ----
    if (tid < NKC) {
        float4 p;
        p.x = sigm(kc_logits[tid * 5 + 0]);
        p.y = sigm(kc_logits[tid * 5 + 1]);
        p.z = sigm(kc_logits[tid * 5 + 2]);
        p.w = sigm(kc_logits[tid * 5 + 3]);
        s_pr[tid] = p;
        s_p4[tid] = sigm(kc_logits[tid * 5 + 4]);
    }

    // ---- direct L2 gathers (concurrent with copy) ----
    int ap = 0, ac = 0;
    if (rt < TLEN) {
        ap = g_assign[pkv];
        ac = g_assign[ckv];
        s_ap[r][rt]  = (unsigned char)ap;
        s_ack[r][rt] = (unsigned char)ac;
    }
    __syncthreads();

    // ---- per-step Moebius tables ----
    if (rt < TLEN) {
        float4 pp = s_pr[ap];
        float o0, o1;
        if (cr > 0.5f) { o0 = pp.z;        o1 = pp.w;        }
        else           { o0 = 1.0f - pp.z; o1 = 1.0f - pp.w; }
        float d10 = o1 - o0;
        float c1  = 1.0f - pp.y - pp.x;
        // pred = (A*s + B) / (C*s + D)
        s_M[r][rt] = make_float4(fmaf(pp.x, d10, c1 * o1), pp.x * o0, d10, o0);
        float4 q = s_pr[ac];
        s_ozw[r][rt] = make_float2(q.w - q.z, q.z);
    }
    __syncthreads();

    // ---- parallel composition: apply maps to the VECTOR (u,v) ----
    if (rt < TLEN) {
        // pass A: out[t], t = rt (t=0 -> no steps taken)
        const int t = rt;
        const int k = (int)s_ack[r][t];
        float u = s_p4[k], v = 1.0f;
        #pragma unroll 7
        for (int i = 1; i < TLEN; i++) {
            float4 M = s_M[r][i];                        // broadcast LDS
            bool take = (i <= t) && ((int)s_ap[r][i] == k);
            float nu = fmaf(M.x, u, M.y * v);
            float nv = fmaf(M.z, u, M.w * v);
            u = take ? nu : u;
            v = take ? nv : v;
        }
        float sf = __fdividef(u, v);
        float2 zw = s_ozw[r][t];
        probs_out[b * TLEN + t] = fmaf(zw.x, sf, zw.y);
    } else if (rt >= 64 && rt < 64 + NKC) {
        // pass B: final state[k], k = rt-64 -> replicated table
        const int k = rt - 64;
        float u = s_p4[k], v = 1.0f;
        #pragma unroll 7
        for (int i = 1; i < TLEN; i++) {
            float4 M = s_M[r][i];
            bool take = ((int)s_ap[r][i] == k);
            float nu = fmaf(M.x, u, M.y * v);
            float nv = fmaf(M.z, u, M.w * v);
            u = take ? nu : u;
            v = take ? nv : v;
        }
        float val = __fdividef(u, v);
        #pragma unroll
        for (int m = 0; m < REP; m++) s_rep[r][k * REP + m] = val;
    }
    __syncthreads();

    // ---- expansion: replicated-table gathers + float4 stores ----
    if (do_state) {
        float4*       o   = (float4*)(state_out + (size_t)b * NOBS);
        const uchar4* a4  = (const uchar4*)s_assign;
        const float*  st  = s_rep[r];
        const int     ofs = tid & (REP - 1);     // lane-spread replica pick
        #pragma unroll
        for (int j = 0; j < 8; j++) {
            uchar4 a = a4[rt + 256 * j];
            o[rt + 256 * j] = make_float4(st[a.x * REP + ofs],
                                          st[a.y * REP + ofs],
                                          st[a.z * REP + ofs],
                                          st[a.w * REP + ofs]);
        }
    }
}

// ============================================================
extern "C" void kernel_launch(void* const* d_in, const int* in_sizes, int n_in,
                              void* d_out, int out_size) {
    const int*    prev_kc   = (const int*)   d_in[0];
    const int*    curr_kc   = (const int*)   d_in[1];
    const float*  prev_corr = (const float*) d_in[2];
    const float*  kc_logits = (const float*) d_in[3];
    const float4* A4        = (const float4*)d_in[4];
    float*        out       = (float*)d_out;

    k1_prep<<<100, 256>>>(A4, prev_kc, curr_kc, prev_corr, kc_logits);

    // Output layout: [probs (256*50) | state (256*8192)] concatenated.
    float* probs_out = out;
    float* state_out = out + BATCH * TLEN;
    int    do_state  = 1;

    if (out_size == BATCH * TLEN) {
        do_state  = 0;
        state_out = out;                 // unused
    } else if (out_size == BATCH * NOBS) {
        void* scratch = nullptr;
        cudaGetSymbolAddress(&scratch, g_probs_scratch);
        probs_out = (float*)scratch;
        state_out = out;
    }

    k2_fused<<<BATCH / 2, 512>>>(prev_kc, curr_kc, prev_corr, kc_logits,
                                 probs_out, state_out, do_state);
}